// round 3
// baseline (speedup 1.0000x reference)
#include <cuda_runtime.h>
#include <type_traits>

#define NT    256
#define HWD   128
#define TW    32          // tile width  (W, contiguous)
#define TH    16          // tile height (H)
#define RAW_S 40          // raw plane row stride (36 used)
#define RAW_H 20          // TH + 4
#define XB_S  32          // xbuf row stride
#define XB_F  (RAW_H * XB_S)   // 640 per field
#define P2_F  (TH * TW)        // 512 per field
#define CZ    16
#define NBLK  (4 * 8 * 64)     // 2048 blocks

__device__ float g_part[NBLK];

__global__ __launch_bounds__(NT, 2)
void ssim_main(const float* __restrict__ xall, const float* __restrict__ yall,
               const float* __restrict__ kern) {
    __shared__ float rawx[RAW_H * RAW_S];
    __shared__ float rawy[RAW_H * RAW_S];
    __shared__ float xb[4 * XB_F];
    __shared__ float p2[4 * P2_F];
    __shared__ float wsm[5];
    __shared__ float wred[8];

    const int tid = threadIdx.x;
    const int w0 = blockIdx.x * TW;
    const int h0 = blockIdx.y * TH;
    const int zc = blockIdx.z & 7;
    const int nc = blockIdx.z >> 3;
    const int z0 = zc * CZ;
    const float* xg = xall + (size_t)nc * (HWD * HWD * HWD);
    const float* yg = yall + (size_t)nc * (HWD * HWD * HWD);

    // separable 1-D weights: plane sums of the 3-D Gaussian
    if (tid < 5) {
        float s = 0.f;
        #pragma unroll
        for (int j = 0; j < 25; ++j) s += kern[tid * 25 + j];
        wsm[tid] = s;
    }
    __syncthreads();
    float wk[5];
    #pragma unroll
    for (int i = 0; i < 5; ++i) wk[i] = wsm[i];

    // rotating z accumulators: [ring slot][field][point]
    float acc[5][4][2];
    #pragma unroll
    for (int s = 0; s < 5; ++s)
        #pragma unroll
        for (int f = 0; f < 4; ++f) { acc[s][f][0] = 0.f; acc[s][f][1] = 0.f; }

    float lsum = 0.f;
    const int lane = tid & 31, wrp = tid >> 5;
    const int pbase = tid * 2;   // each thread owns 2 consecutive output points

    auto step = [&](int i, auto phc) {
        constexpr int PH = decltype(phc)::value;   // PH == i % 5
        const int t = z0 - 2 + i;                   // absolute plane index
        const bool inz = (unsigned)t < (unsigned)HWD;
        if (inz) {
            // ---- load raw plane (x,y), fuse (v+1)*0.5, zero-pad H/W borders ----
            const float* xp = xg + (size_t)t * (HWD * HWD);
            const float* yp = yg + (size_t)t * (HWD * HWD);
            #pragma unroll
            for (int rr = 0; rr < RAW_H / (NT / 32) + 1; ++rr) {
                int r = wrp + rr * (NT / 32);
                if (r < RAW_H) {
                    int hg = h0 + r - 2;
                    bool okh = (unsigned)hg < (unsigned)HWD;
                    int wg = w0 + lane - 2;
                    float xv = 0.f, yv = 0.f;
                    if (okh && (unsigned)wg < (unsigned)HWD) {
                        int o = hg * HWD + wg;
                        xv = (xp[o] + 1.f) * 0.5f;
                        yv = (yp[o] + 1.f) * 0.5f;
                    }
                    rawx[r * RAW_S + lane] = xv;
                    rawy[r * RAW_S + lane] = yv;
                    if (lane < 4) {
                        int wg2 = wg + 32;
                        float xv2 = 0.f, yv2 = 0.f;
                        if (okh && (unsigned)wg2 < (unsigned)HWD) {
                            int o = hg * HWD + wg2;
                            xv2 = (xp[o] + 1.f) * 0.5f;
                            yv2 = (yp[o] + 1.f) * 0.5f;
                        }
                        rawx[r * RAW_S + lane + 32] = xv2;
                        rawy[r * RAW_S + lane + 32] = yv2;
                    }
                }
            }
            __syncthreads();

            // ---- x-pass: 160 jobs (20 rows x 8 col-groups), 4 fields, 4 outputs each ----
            if (tid < 160) {
                int r = tid >> 3, cb = tid & 7;
                const float* rx = rawx + r * RAW_S + cb * 4;
                const float* ry = rawy + r * RAW_S + cb * 4;
                float4 xa = *(const float4*)rx, xc = *(const float4*)(rx + 4);
                float4 ya = *(const float4*)ry, yc = *(const float4*)(ry + 4);
                float xv[8] = {xa.x, xa.y, xa.z, xa.w, xc.x, xc.y, xc.z, xc.w};
                float yv[8] = {ya.x, ya.y, ya.z, ya.w, yc.x, yc.y, yc.z, yc.w};
                float sv[8], cv[8];
                #pragma unroll
                for (int j = 0; j < 8; ++j) {
                    sv[j] = xv[j] * xv[j] + yv[j] * yv[j];
                    cv[j] = xv[j] * yv[j];
                }
                float o0[4], o1[4], o2[4], o3[4];
                #pragma unroll
                for (int c = 0; c < 4; ++c) {
                    float a0 = 0.f, a1 = 0.f, a2 = 0.f, a3 = 0.f;
                    #pragma unroll
                    for (int k = 0; k < 5; ++k) {
                        float w = wk[k];
                        a0 += w * xv[c + k];
                        a1 += w * yv[c + k];
                        a2 += w * sv[c + k];
                        a3 += w * cv[c + k];
                    }
                    o0[c] = a0; o1[c] = a1; o2[c] = a2; o3[c] = a3;
                }
                int ob = r * XB_S + cb * 4;
                *(float4*)&xb[0 * XB_F + ob] = make_float4(o0[0], o0[1], o0[2], o0[3]);
                *(float4*)&xb[1 * XB_F + ob] = make_float4(o1[0], o1[1], o1[2], o1[3]);
                *(float4*)&xb[2 * XB_F + ob] = make_float4(o2[0], o2[1], o2[2], o2[3]);
                *(float4*)&xb[3 * XB_F + ob] = make_float4(o3[0], o3[1], o3[2], o3[3]);
            }
            __syncthreads();

            // ---- y-pass: 256 jobs (4 fields x 8 row-pairs x 8 col-groups) ----
            {
                int f = tid >> 6, rg = (tid >> 3) & 7, cb = tid & 7;
                const float* src = xb + f * XB_F + cb * 4;
                float vr[6][4];
                #pragma unroll
                for (int k = 0; k < 6; ++k) {
                    float4 v = *(const float4*)&src[(rg * 2 + k) * XB_S];
                    vr[k][0] = v.x; vr[k][1] = v.y; vr[k][2] = v.z; vr[k][3] = v.w;
                }
                float u0[4], u1[4];
                #pragma unroll
                for (int c = 0; c < 4; ++c) {
                    float a0 = 0.f, a1 = 0.f;
                    #pragma unroll
                    for (int k = 0; k < 5; ++k) {
                        float w = wk[k];
                        a0 += w * vr[k][c];
                        a1 += w * vr[k + 1][c];
                    }
                    u0[c] = a0; u1[c] = a1;
                }
                int ob = f * P2_F + (rg * 2) * TW + cb * 4;
                *(float4*)&p2[ob]      = make_float4(u0[0], u0[1], u0[2], u0[3]);
                *(float4*)&p2[ob + TW] = make_float4(u1[0], u1[1], u1[2], u1[3]);
            }
            __syncthreads();

            // ---- z-accumulate into rotating registers ----
            {
                float2 v0 = *(const float2*)&p2[0 * P2_F + pbase];
                float2 v1 = *(const float2*)&p2[1 * P2_F + pbase];
                float2 v2 = *(const float2*)&p2[2 * P2_F + pbase];
                float2 v3 = *(const float2*)&p2[3 * P2_F + pbase];
                #pragma unroll
                for (int k = 0; k < 5; ++k) {
                    const int oz = i - 4 + k;
                    if (oz >= 0 && oz < CZ) {
                        const int S = (PH + 1 + k) % 5;
                        const float wv = wk[4 - k];
                        acc[S][0][0] += wv * v0.x;  acc[S][0][1] += wv * v0.y;
                        acc[S][1][0] += wv * v1.x;  acc[S][1][1] += wv * v1.y;
                        acc[S][2][0] += wv * v2.x;  acc[S][2][1] += wv * v2.y;
                        acc[S][3][0] += wv * v3.x;  acc[S][3][1] += wv * v3.y;
                    }
                }
            }
        }
        // ---- finalize output z = z0 + (i-4): this plane was its last contributor ----
        if (i >= 4) {
            const int S = (PH + 1) % 5;
            const float c1 = 1e-4f, c2 = 9e-4f;
            #pragma unroll
            for (int pt = 0; pt < 2; ++pt) {
                float mu1 = acc[S][0][pt], mu2 = acc[S][1][pt];
                float ss  = acc[S][2][pt], cc  = acc[S][3][pt];
                float mu1s = mu1 * mu1, mu2s = mu2 * mu2, mu12 = mu1 * mu2;
                float s12 = cc - mu12;
                float sdn = ss - mu1s - mu2s;
                float num = (2.f * mu12 + c1) * (2.f * s12 + c2);
                float den = (mu1s + mu2s + c1) * (sdn + c2);
                lsum += __fdividef(num, den);
                acc[S][0][pt] = 0.f; acc[S][1][pt] = 0.f;
                acc[S][2][pt] = 0.f; acc[S][3][pt] = 0.f;
            }
        }
    };

    #pragma unroll 1
    for (int ii = 0; ii < CZ + 4; ii += 5) {
        step(ii + 0, std::integral_constant<int, 0>{});
        step(ii + 1, std::integral_constant<int, 1>{});
        step(ii + 2, std::integral_constant<int, 2>{});
        step(ii + 3, std::integral_constant<int, 3>{});
        step(ii + 4, std::integral_constant<int, 4>{});
    }

    // ---- block reduction -> per-block partial ----
    #pragma unroll
    for (int o = 16; o > 0; o >>= 1)
        lsum += __shfl_down_sync(0xffffffffu, lsum, o);
    if (lane == 0) wred[wrp] = lsum;
    __syncthreads();
    if (tid < 32) {
        float v = (tid < 8) ? wred[tid] : 0.f;
        #pragma unroll
        for (int o = 4; o > 0; o >>= 1)
            v += __shfl_down_sync(0xffffffffu, v, o);
        if (tid == 0) {
            int bid = blockIdx.x + 4 * (blockIdx.y + 8 * blockIdx.z);
            g_part[bid] = v;
        }
    }
}

__global__ void ssim_fin(float* __restrict__ out, int n) {
    __shared__ double sred[8];
    __shared__ float vout;
    const int tid = threadIdx.x;
    const int lane = tid & 31, wrp = tid >> 5;
    double s = 0.0;
    for (int i = tid; i < NBLK; i += 256) s += (double)g_part[i];
    #pragma unroll
    for (int o = 16; o > 0; o >>= 1)
        s += __shfl_down_sync(0xffffffffu, s, o);
    if (lane == 0) sred[wrp] = s;
    __syncthreads();
    if (tid < 32) {
        double v = (tid < 8) ? sred[tid] : 0.0;
        #pragma unroll
        for (int o = 4; o > 0; o >>= 1)
            v += __shfl_down_sync(0xffffffffu, v, o);
        if (tid == 0) vout = (float)(v / 16777216.0);
    }
    __syncthreads();
    float v = vout;
    for (int i = tid; i < n; i += 256) out[i] = v;
}

extern "C" void kernel_launch(void* const* d_in, const int* in_sizes, int n_in,
                              void* d_out, int out_size) {
    const float* x = (const float*)d_in[0];
    const float* y = (const float*)d_in[1];
    const float* k = (const float*)d_in[2];
    float* out = (float*)d_out;

    dim3 grid(HWD / TW, HWD / TH, 8 * 8);   // 4 x 8 x 64 = 2048 blocks
    ssim_main<<<grid, NT>>>(x, y, k);
    ssim_fin<<<1, 256>>>(out, out_size);
}